// round 15
// baseline (speedup 1.0000x reference)
#include <cuda_runtime.h>
#include <cuda_fp16.h>

#define B 8
#define N 2048
#define D 64
#define ALPHA 0.2f

// Scratch: h fp16 [B,N,D]; per-row exp packs (e^s, e^{(a-1)s}) / (e^t, e^{at});
// colsum accumulators + flags.
__device__ __align__(16) __half  g_hh[B * N * D];
__device__ __align__(16) float2  g_se[B * N];
__device__ __align__(16) float2  g_te[B * N];
__device__ __align__(16) float   g_S[B * D];    // finalized colsums
__device__ __align__(16) float   g_S2[B * D];   // atomic accumulators (zero-init, self-resetting)
__device__ int g_cnt[B];                        // zero-init, self-resetting

// Fused: h = x@W (fp16 out), colsums S (atomics + last-block finalize),
// s/t row-dots + exp packs. Block (64,4); 32 rows/block; grid = B*N/32 = 512.
__global__ __launch_bounds__(256) void k_h(const float* __restrict__ x,
                                           const float* __restrict__ W,
                                           const float* __restrict__ a) {
    __shared__ float Ws[64 * 64];
    __shared__ float xs[32 * 64];
    __shared__ float red[4][64];
    __shared__ float redS[8][4][2];
    __shared__ float redT[8][4][2];
    __shared__ int isLast;
    int tx = threadIdx.x, ty = threadIdx.y;
    int tid = ty * 64 + tx;

    const float4* W4 = (const float4*)W;
    float4* Ws4 = (float4*)Ws;
    for (int k = tid; k < 1024; k += 256) Ws4[k] = W4[k];
    int rowBase = blockIdx.x * 32;               // flattened over B*N (32 | N)
    int b = rowBase / N;
    const float4* x4 = ((const float4*)x) + rowBase * 16;
    float4* xs4 = (float4*)xs;
    for (int k = tid; k < 512; k += 256) xs4[k] = x4[k];
    __syncthreads();

    float a0 = a[tx];
    float a1 = a[64 + tx];
    float accs[8];
#pragma unroll
    for (int rt = 0; rt < 8; rt++) accs[rt] = 0.f;
#pragma unroll
    for (int i4 = 0; i4 < 16; i4++) {
        float w0 = Ws[(i4 * 4 + 0) * 64 + tx];
        float w1 = Ws[(i4 * 4 + 1) * 64 + tx];
        float w2 = Ws[(i4 * 4 + 2) * 64 + tx];
        float w3 = Ws[(i4 * 4 + 3) * 64 + tx];
#pragma unroll
        for (int rt = 0; rt < 8; rt++) {
            float4 xv = xs4[(rt * 4 + ty) * 16 + i4];
            accs[rt] = fmaf(xv.x, w0, accs[rt]);
            accs[rt] = fmaf(xv.y, w1, accs[rt]);
            accs[rt] = fmaf(xv.z, w2, accs[rt]);
            accs[rt] = fmaf(xv.w, w3, accs[rt]);
        }
    }
    float part = 0.f;
#pragma unroll
    for (int rt = 0; rt < 8; rt++) {
        g_hh[(rowBase + rt * 4 + ty) * 64 + tx] = __float2half_rn(accs[rt]);
        part += accs[rt];
    }
    int lane = tid & 31, half = tx >> 5;
#pragma unroll
    for (int rt = 0; rt < 8; rt++) {
        float sp = accs[rt] * a0;
        float tp = accs[rt] * a1;
#pragma unroll
        for (int o = 16; o > 0; o >>= 1) {
            sp += __shfl_xor_sync(0xffffffffu, sp, o);
            tp += __shfl_xor_sync(0xffffffffu, tp, o);
        }
        if (lane == 0) { redS[rt][ty][half] = sp; redT[rt][ty][half] = tp; }
    }
    red[ty][tx] = part;
    __syncthreads();
    if (tid < 32) {
        int rt = tid >> 2, tyy = tid & 3;
        float s = redS[rt][tyy][0] + redS[rt][tyy][1];
        float t = redT[rt][tyy][0] + redT[rt][tyy][1];
        int r = rowBase + rt * 4 + tyy;
        // (e^s, e^{(alpha-1)s}) so  f1*max(e^t, r*e^{at}) = max(e^{s+t}, e^{a(s+t)})
        g_se[r] = make_float2(__expf(s), __expf((ALPHA - 1.f) * s));
        g_te[r] = make_float2(__expf(t), __expf(ALPHA * t));
    }
    if (ty == 0) {
        float ssum = red[0][tx] + red[1][tx] + red[2][tx] + red[3][tx];
        atomicAdd(&g_S2[b * 64 + tx], ssum);
    }
    __threadfence();             // order this thread's g_S2 atomic
    __syncthreads();             // ...and everyone's, before the signal
    if (tid == 0) {
        int old = atomicAdd(&g_cnt[b], 1);
        isLast = (old == 63);
        if (isLast) __threadfence();   // acquire before reading g_S2
    }
    __syncthreads();
    if (isLast && tid < 64) {
        g_S[b * 64 + tid] = g_S2[b * 64 + tid];
        g_S2[b * 64 + tid] = 0.f;
        if (tid == 0) g_cnt[b] = 0;
    }
}

// Packed f32x2 helpers (FFMA2 per SASS_QUICKREF: only reachable via PTX)
__device__ __forceinline__ unsigned long long pack2(float lo, float hi) {
    unsigned long long p;
    asm("mov.b64 %0, {%1, %2};" : "=l"(p) : "f"(lo), "f"(hi));
    return p;
}
__device__ __forceinline__ void ffma2(unsigned long long& acc,
                                      unsigned long long m,
                                      unsigned long long c2) {
    asm("fma.rn.f32x2 %0, %1, %2, %0;" : "+l"(acc) : "l"(m), "l"(c2));
}

// One block per row i. Phase 1: atomic-free sorted neighbor compaction.
// Phase 2: warp b = batch b; 4 neighbors/warp-iter (quarter-warp each).
// c = fma(e^s, max(e^t, e^{(a-1)s} e^{at}), -1); accumulation via FFMA2.
__global__ __launch_bounds__(256) void k_main(const float* __restrict__ adj,
                                              const float* __restrict__ bias,
                                              float* __restrict__ out) {
    __shared__ unsigned short nbr[N + 8];
    __shared__ float sh_f1[8], sh_r[8];
    __shared__ int sh_wtot[8], sh_wbase[8], sh_cnt;
    int i = blockIdx.x, tid = threadIdx.x;
    int wid = tid >> 5, lane = tid & 31;

    if (tid < 8) {
        float2 se = g_se[tid * N + i];
        sh_f1[tid] = se.x; sh_r[tid] = se.y;
    }

    // ---- Phase 1: scan 8 contiguous adj entries per thread ----
    const float4* arow4 = (const float4*)(adj + (size_t)i * N);
    float4 v0 = arow4[tid * 2];
    float4 v1 = arow4[tid * 2 + 1];
    int j0 = tid * 8;
    unsigned bm = 0;
    bm |= (v0.x != 0.f) ? 1u : 0u;
    bm |= (v0.y != 0.f) ? 2u : 0u;
    bm |= (v0.z != 0.f) ? 4u : 0u;
    bm |= (v0.w != 0.f) ? 8u : 0u;
    bm |= (v1.x != 0.f) ? 16u : 0u;
    bm |= (v1.y != 0.f) ? 32u : 0u;
    bm |= (v1.z != 0.f) ? 64u : 0u;
    bm |= (v1.w != 0.f) ? 128u : 0u;
    if ((unsigned)(i - j0) < 8u) bm |= 1u << (i - j0);   // forced diagonal
    int lc = __popc(bm);
    int pre = lc;
#pragma unroll
    for (int o = 1; o < 32; o <<= 1) {
        int u = __shfl_up_sync(0xffffffffu, pre, o);
        if (lane >= o) pre += u;
    }
    if (lane == 31) sh_wtot[wid] = pre;
    __syncthreads();
    if (tid == 0) {
        int run = 0;
#pragma unroll
        for (int w = 0; w < 8; w++) { sh_wbase[w] = run; run += sh_wtot[w]; }
        sh_cnt = run;
    }
    __syncthreads();
    int base = sh_wbase[wid] + pre - lc;
#pragma unroll
    for (int k = 0; k < 8; k++) {
        if (bm & (1u << k))
            nbr[base + __popc(bm & ((1u << k) - 1u))] = (unsigned short)(j0 + k);
    }
    __syncthreads();
    int cnt = sh_cnt;

    // ---- Phase 2: gather-accumulate, 4 neighbors per warp-iteration ----
    int b = wid, sub = lane >> 3, d8 = lane & 7;
    float f1 = sh_f1[b], rr = sh_r[b];
    const float2* teb = (const float2*)g_te + b * N;
    const char* hb = (const char*)g_hh + (size_t)(b * N * D) * 2 + d8 * 16;
    unsigned long long p01 = 0ull, p23 = 0ull, p45 = 0ull, p67 = 0ull;
    float z = 0.f;
    int full = cnt & ~3;
#pragma unroll 8
    for (int k0 = 0; k0 < full; k0 += 4) {
        int j = (int)nbr[k0 + sub];
        float2 te = teb[j];
        float c = fmaf(f1, fmaxf(te.x, rr * te.y), -1.f);
        unsigned long long c2 = pack2(c, c);
        uint4 hv = *(const uint4*)(hb + (j << 7));   // 16B of the 128B row
        float2 q0 = __half22float2(*(const __half2*)&hv.x);
        float2 q1 = __half22float2(*(const __half2*)&hv.y);
        float2 q2 = __half22float2(*(const __half2*)&hv.z);
        float2 q3 = __half22float2(*(const __half2*)&hv.w);
        ffma2(p01, pack2(q0.x, q0.y), c2);
        ffma2(p23, pack2(q1.x, q1.y), c2);
        ffma2(p45, pack2(q2.x, q2.y), c2);
        ffma2(p67, pack2(q3.x, q3.y), c2);
        z += c;
    }
    if (full < cnt) {            // tail: 1-3 neighbors, predicated
        int k = full + sub;
        bool valid = k < cnt;
        int j = valid ? (int)nbr[k] : 0;
        float2 te = teb[j];
        float c = fmaf(f1, fmaxf(te.x, rr * te.y), -1.f);
        c = valid ? c : 0.f;
        unsigned long long c2 = pack2(c, c);
        uint4 hv = *(const uint4*)(hb + (j << 7));
        float2 q0 = __half22float2(*(const __half2*)&hv.x);
        float2 q1 = __half22float2(*(const __half2*)&hv.y);
        float2 q2 = __half22float2(*(const __half2*)&hv.z);
        float2 q3 = __half22float2(*(const __half2*)&hv.w);
        ffma2(p01, pack2(q0.x, q0.y), c2);
        ffma2(p23, pack2(q1.x, q1.y), c2);
        ffma2(p45, pack2(q2.x, q2.y), c2);
        ffma2(p67, pack2(q3.x, q3.y), c2);
        z += c;
    }
    // unpack packed accumulators
    float a0, a1, a2, a3, a4, a5, a6, a7;
    asm("mov.b64 {%0, %1}, %2;" : "=f"(a0), "=f"(a1) : "l"(p01));
    asm("mov.b64 {%0, %1}, %2;" : "=f"(a2), "=f"(a3) : "l"(p23));
    asm("mov.b64 {%0, %1}, %2;" : "=f"(a4), "=f"(a5) : "l"(p45));
    asm("mov.b64 {%0, %1}, %2;" : "=f"(a6), "=f"(a7) : "l"(p67));
    // reduce across the 4 sub-groups (lane bits 3,4)
#pragma unroll
    for (int o = 8; o <= 16; o <<= 1) {
        a0 += __shfl_xor_sync(0xffffffffu, a0, o);
        a1 += __shfl_xor_sync(0xffffffffu, a1, o);
        a2 += __shfl_xor_sync(0xffffffffu, a2, o);
        a3 += __shfl_xor_sync(0xffffffffu, a3, o);
        a4 += __shfl_xor_sync(0xffffffffu, a4, o);
        a5 += __shfl_xor_sync(0xffffffffu, a5, o);
        a6 += __shfl_xor_sync(0xffffffffu, a6, o);
        a7 += __shfl_xor_sync(0xffffffffu, a7, o);
        z  += __shfl_xor_sync(0xffffffffu, z, o);
    }
    if (sub == 0) {                       // lanes 0-7: dims d8*8 .. d8*8+7
        float inv = 1.f / ((float)N + z);
        const float4* S4 = (const float4*)&g_S[b * 64 + d8 * 8];
        const float4* b4 = (const float4*)&bias[d8 * 8];
        float4 S0 = S4[0], S1 = S4[1], bb0 = b4[0], bb1 = b4[1];
        float4 o0, o1;
        o0.x = (S0.x + a0) * inv + bb0.x;
        o0.y = (S0.y + a1) * inv + bb0.y;
        o0.z = (S0.z + a2) * inv + bb0.z;
        o0.w = (S0.w + a3) * inv + bb0.w;
        o1.x = (S1.x + a4) * inv + bb1.x;
        o1.y = (S1.y + a5) * inv + bb1.y;
        o1.z = (S1.z + a6) * inv + bb1.z;
        o1.w = (S1.w + a7) * inv + bb1.w;
        float4* op = (float4*)(out + (size_t)(b * N + i) * 64 + d8 * 8);
        op[0] = o0;
        op[1] = o1;
    }
}

extern "C" void kernel_launch(void* const* d_in, const int* in_sizes, int n_in,
                              void* d_out, int out_size) {
    const float* x    = (const float*)d_in[0];  // [B,N,64]
    const float* adj  = (const float*)d_in[1];  // [N,N]
    const float* W    = (const float*)d_in[2];  // [64,64]
    const float* a    = (const float*)d_in[3];  // [128,1]
    const float* bias = (const float*)d_in[4];  // [64]
    float* out = (float*)d_out;                 // [B,N,64]

    k_h<<<(B * N) / 32, dim3(64, 4)>>>(x, W, a);
    k_main<<<N, 256>>>(adj, bias, out);
}